// round 10
// baseline (speedup 1.0000x reference)
#include <cuda_runtime.h>
#include <math_constants.h>

#define NBOX   10647          // 52*52*3 + 26*26*3 + 13*13*3
#define NBATCH 4
#define DET_ELEMS (NBATCH*NBOX*6)
#define CAP    256            // per-(batch,class) bucket capacity (mean ~66, >20 sigma safe)

#define QTOT    845           // float4-quads over scale1+scale2 spatial (676 + 169)
#define DEC_QUAD  (3*NBATCH*QTOT)            // 10140 quad threads (scales 1,2)
#define DEC_TOTAL (DEC_QUAD + 3*NBATCH*169)  // + 2028 scalar threads (scale 3) = 12168

// Scratch (__device__ globals — zero-initialized at load; nms re-zeroes g_cnt after use)
__device__ int   g_cnt[NBATCH*80];
__device__ float g_bucket[NBATCH*80*CAP*8];  // b0,b1,b2,b3 | area,conf,idx,pad

__constant__ float c_anch[3][3][2] = {
  {{10.f,13.f},{16.f,30.f},{33.f,23.f}},
  {{30.f,61.f},{62.f,45.f},{59.f,119.f}},
  {{116.f,90.f},{156.f,198.f},{373.f,326.f}}
};

__device__ __forceinline__ float sigmoidf_(float x){ return 1.0f/(1.0f + expf(-x)); }

// Full per-box epilogue: reference math (same op order), det/keep stores, bucket append.
__device__ __forceinline__ void emit_box(
    float tx, float ty, float tw, float th, float tc,
    int s, int W, float stride, int si, int a, int b, int bi, int nbase,
    float* __restrict__ det_out, float* __restrict__ keep_out)
{
    int h = s / W, w = s - h*W;
    float x  = (sigmoidf_(tx) + (float)w) * stride;
    float y  = (sigmoidf_(ty) + (float)h) * stride;
    float bw = expf(tw) * c_anch[si][a][0] * stride;
    float bh = expf(th) * c_anch[si][a][1] * stride;
    float conf = sigmoidf_(tc);

    float b0 = x - bw*0.5f, b1 = x + bw*0.5f;   // both from x (reference quirk)
    float b2 = y - bh*0.5f, b3 = y + bh*0.5f;   // both from y
    float area = fmaxf(b2-b0+1.0f, 0.0f) * fmaxf(b3-b1+1.0f, 0.0f);

    int n = nbase + (w*W + h)*3 + a;            // reference flatten order (W==H)
    long o = (long)b*NBOX + n;
    float* dp = det_out + o*6;
    dp[0]=b0; dp[1]=b1; dp[2]=b2; dp[3]=b3; dp[4]=conf; dp[5]=(float)bi;
    keep_out[o] = 0.0f;                          // NMS overwrites valid boxes

    if (conf > 0.5f){
        int bc = b*80 + bi;
        int pos = atomicAdd(&g_cnt[bc], 1);
        if (pos < CAP){
            float4* rec = (float4*)(g_bucket + ((long)bc*CAP + pos)*8);
            rec[0] = make_float4(b0, b1, b2, b3);
            rec[1] = make_float4(area, conf, (float)n, 0.0f);
        }
    }
}

// Quad decode: one thread per 4 consecutive spatial cells (scales 1,2; HW%4==0,
// 16B-aligned) -> 85 independent LDG.128, 512B-contiguous per warp-load.
// Scale 3 (HW=169, odd) decoded by a scalar tail, one thread per box.
__global__ void decode_kernel(const float* __restrict__ f1,
                              const float* __restrict__ f2,
                              const float* __restrict__ f3,
                              float* __restrict__ det_out,
                              float* __restrict__ keep_out){
    int T = blockIdx.x*blockDim.x + threadIdx.x;
    if (T < DEC_QUAD){
        int a = T / (NBATCH*QTOT);
        int r = T - a*(NBATCH*QTOT);
        int b = r / QTOT;
        int q = r - b*QTOT;
        const float* feat; int W; float stride; int nbase; int HW; int si; int s4;
        if (q < 676){ feat=f1; W=52; stride=8.0f;  nbase=0;    HW=2704; si=0; s4=q*4; }
        else        { feat=f2; W=26; stride=16.0f; nbase=8112; HW=676;  si=1; s4=(q-676)*4; }

        const float* fc = feat + ((long)b*255 + a*85)*HW + s4;
        float4 vx = *(const float4*)(fc);
        float4 vy = *(const float4*)(fc + HW);
        float4 vw = *(const float4*)(fc + 2*HW);
        float4 vh = *(const float4*)(fc + 3*HW);
        float4 vc = *(const float4*)(fc + 4*HW);

        // Streaming argmax, e increasing + strict '>' -> exact first-occurrence
        // argmax (sigmoid monotone, so raw logits are equivalent).
        const float* fcls = fc + 5L*HW;
        float4 best = *(const float4*)(fcls);
        int bi0=0, bi1=0, bi2=0, bi3=0;
        #pragma unroll 8
        for (int e = 1; e < 80; e++){
            float4 v = *(const float4*)(fcls + (long)e*HW);
            if (v.x > best.x){ best.x = v.x; bi0 = e; }
            if (v.y > best.y){ best.y = v.y; bi1 = e; }
            if (v.z > best.z){ best.z = v.z; bi2 = e; }
            if (v.w > best.w){ best.w = v.w; bi3 = e; }
        }
        emit_box(vx.x,vy.x,vw.x,vh.x,vc.x, s4+0, W, stride, si,a,b, bi0, nbase, det_out, keep_out);
        emit_box(vx.y,vy.y,vw.y,vh.y,vc.y, s4+1, W, stride, si,a,b, bi1, nbase, det_out, keep_out);
        emit_box(vx.z,vy.z,vw.z,vh.z,vc.z, s4+2, W, stride, si,a,b, bi2, nbase, det_out, keep_out);
        emit_box(vx.w,vy.w,vw.w,vh.w,vc.w, s4+3, W, stride, si,a,b, bi3, nbase, det_out, keep_out);
    }
    else if (T < DEC_TOTAL){
        int idx = T - DEC_QUAD;
        int a = idx / (NBATCH*169);
        int r = idx - a*(NBATCH*169);
        int b = r / 169;
        int s = r - b*169;
        const float* fc = f3 + ((long)b*255 + a*85)*169 + s;
        float tx = fc[0], ty = fc[169], tw = fc[338], th = fc[507], tc = fc[676];
        const float* fcls = fc + 5*169;
        float best = fcls[0]; int bi = 0;
        #pragma unroll 8
        for (int e = 1; e < 80; e++){
            float v = fcls[e*169];
            if (v > best){ best = v; bi = e; }
        }
        emit_box(tx,ty,tw,th,tc, s, 13, 32.0f, 2, a, b, bi, 10140, det_out, keep_out);
    }
}

// One block per bucket, 8 warps. Each warp register-holds ALL j-records
// (3 slots x 32 lanes = 96 >= cnt in practice; sentinel-padded). i-records are
// shfl-broadcast from the holder lane. No smem staging, no dependent phases.
// cnt > 96 falls back to a generic global-memory scan (statistically never).
#define NMS_THREADS 256
__global__ void nms_kernel(float* __restrict__ keep_out){
    int bc = blockIdx.x;                         // b*80 + c
    int b  = bc / 80;
    int t  = threadIdx.x, lane = t & 31, warp = t >> 5;

    int cnt = g_cnt[bc]; if (cnt > CAP) cnt = CAP;
    __syncthreads();                             // all reads done before reset
    if (t == 0) g_cnt[bc] = 0;                   // restore zero for next call
    if (cnt == 0) return;

    const float4* base = (const float4*)(g_bucket + (long)bc*CAP*8);

    if (cnt <= 96){
        // ---- fast path: j-records in registers ----
        float4 jl0, jl1, jl2; float2 ja0, ja1, ja2; float ji0, ji1, ji2;
        {
            int j = lane;
            if (j < cnt){ float4 lo=base[2*j], hi=base[2*j+1]; jl0=lo; ja0=make_float2(hi.x,hi.y); ji0=hi.z; }
            else { jl0=make_float4(0,0,0,0); ja0=make_float2(0.f,-CUDART_INF_F); ji0=0.f; }
            j = 32 + lane;
            if (j < cnt){ float4 lo=base[2*j], hi=base[2*j+1]; jl1=lo; ja1=make_float2(hi.x,hi.y); ji1=hi.z; }
            else { jl1=make_float4(0,0,0,0); ja1=make_float2(0.f,-CUDART_INF_F); ji1=0.f; }
            j = 64 + lane;
            if (j < cnt){ float4 lo=base[2*j], hi=base[2*j+1]; jl2=lo; ja2=make_float2(hi.x,hi.y); ji2=hi.z; }
            else { jl2=make_float4(0,0,0,0); ja2=make_float2(0.f,-CUDART_INF_F); ji2=0.f; }
        }
        for (int i = warp; i < cnt; i += NMS_THREADS/32){
            int hl = i & 31, sl = i >> 5;        // holder lane, slot (warp-uniform sl)
            float4 src = (sl==0) ? jl0 : (sl==1) ? jl1 : jl2;
            float2 sac = (sl==0) ? ja0 : (sl==1) ? ja1 : ja2;
            float  sid = (sl==0) ? ji0 : (sl==1) ? ji1 : ji2;
            float4 il; float2 ia;
            il.x = __shfl_sync(0xFFFFFFFFu, src.x, hl);
            il.y = __shfl_sync(0xFFFFFFFFu, src.y, hl);
            il.z = __shfl_sync(0xFFFFFFFFu, src.z, hl);
            il.w = __shfl_sync(0xFFFFFFFFu, src.w, hl);
            ia.x = __shfl_sync(0xFFFFFFFFu, sac.x, hl);
            ia.y = __shfl_sync(0xFFFFFFFFu, sac.y, hl);
            float idxf = __shfl_sync(0xFFFFFFFFu, sid, hl);

            bool p = false;
            #pragma unroll
            for (int s = 0; s < 3; s++){
                float4 jl = (s==0)?jl0:(s==1)?jl1:jl2;
                float2 ja = (s==0)?ja0:(s==1)?ja1:ja2;
                if (ia.y < ja.y){                // conf_i < conf_j (kills pads & j==i)
                    float wI = fmaxf(fminf(il.z, jl.z) - fmaxf(il.x, jl.x) + 1.0f, 0.0f);
                    float hI = fmaxf(fminf(il.w, jl.w) - fmaxf(il.y, jl.y) + 1.0f, 0.0f);
                    float inter = wI * hI;
                    float uni = ia.x + ja.x - inter;     // same op order as reference
                    float thr = 0.4f * uni;
                    if (inter > thr*0.9999f)             // certainly-false cut
                        p |= (inter > thr*1.0001f) ? true
                             : (inter / uni > 0.4f);     // exact IEEE div in the band
                }
            }
            bool found = __any_sync(0xFFFFFFFFu, p);
            if (lane == 0)
                keep_out[(long)b*NBOX + (int)idxf] = found ? 1.0f : 0.0f;
        }
    } else {
        // ---- generic fallback (cnt > 96): scan all j from global ----
        for (int i = warp; i < cnt; i += NMS_THREADS/32){
            float4 il = base[2*i]; float4 ih = base[2*i+1];
            float areai = ih.x, confi = ih.y;
            bool found = false;
            for (int j0 = 0; j0 < cnt && !found; j0 += 32){
                int j = j0 + lane;
                bool p = false;
                if (j < cnt){
                    float4 jh = base[2*j+1];
                    if (confi < jh.y){
                        float4 jlo = base[2*j];
                        float wI = fmaxf(fminf(il.z, jlo.z) - fmaxf(il.x, jlo.x) + 1.0f, 0.0f);
                        float hI = fmaxf(fminf(il.w, jlo.w) - fmaxf(il.y, jlo.y) + 1.0f, 0.0f);
                        float inter = wI * hI;
                        float uni = areai + jh.x - inter;
                        float thr = 0.4f * uni;
                        if (inter > thr*0.9999f)
                            p = (inter > thr*1.0001f) ? true : (inter / uni > 0.4f);
                    }
                }
                if (__any_sync(0xFFFFFFFFu, p)) found = true;
            }
            if (lane == 0)
                keep_out[(long)b*NBOX + (int)ih.z] = found ? 1.0f : 0.0f;
        }
    }
}

extern "C" void kernel_launch(void* const* d_in, const int* in_sizes, int n_in,
                              void* d_out, int out_size){
    const float* f1 = (const float*)d_in[0];   // (4,255,52,52)
    const float* f2 = (const float*)d_in[1];   // (4,255,26,26)
    const float* f3 = (const float*)d_in[2];   // (4,255,13,13)
    float* det  = (float*)d_out;               // (4,10647,6) then keep (4,10647)
    float* keep = det + DET_ELEMS;

    decode_kernel<<<(DEC_TOTAL + 63)/64, 64>>>(f1, f2, f3, det, keep);
    nms_kernel   <<<NBATCH*80, NMS_THREADS>>>(keep);
}

// round 11
// speedup vs baseline: 1.2544x; 1.2544x over previous
#include <cuda_runtime.h>
#include <math_constants.h>

#define NBOX   10647          // 52*52*3 + 26*26*3 + 13*13*3
#define NBATCH 4
#define DET_ELEMS (NBATCH*NBOX*6)
#define CAP    256            // per-(batch,class) bucket capacity (mean ~66, >20 sigma safe)

#define QTOT    845           // float4-quads over scale1+scale2 spatial (676 + 169)
#define NQT     (3*NBATCH*QTOT)              // 10140 quad-teams
#define QTHREADS (NQT*4)                     // 40560 quad lanes
#define QEND    (((QTHREADS)+31) & ~31)      // 40576: pad to warp boundary
#define S3THREADS (3*NBATCH*169)             // 2028 scalar threads (scale 3)
#define DEC_TOTAL (QEND + S3THREADS)         // 42604

// Scratch (__device__ globals — zero-initialized at load; nms re-zeroes g_cnt after use)
__device__ int   g_cnt[NBATCH*80];
__device__ float g_bucket[NBATCH*80*CAP*8];  // b0,b1,b2,b3 | area,conf,idx,pad

__constant__ float c_anch[3][3][2] = {
  {{10.f,13.f},{16.f,30.f},{33.f,23.f}},
  {{30.f,61.f},{62.f,45.f},{59.f,119.f}},
  {{116.f,90.f},{156.f,198.f},{373.f,326.f}}
};

__device__ __forceinline__ float sigmoidf_(float x){ return 1.0f/(1.0f + expf(-x)); }
__device__ __forceinline__ float getc(float4 v, int k){
    return (k==0)?v.x : (k==1)?v.y : (k==2)?v.z : v.w;
}

// Full per-box epilogue: reference math (same op order), det/keep stores, bucket append.
__device__ __forceinline__ void emit_box(
    float tx, float ty, float tw, float th, float tc,
    int s, int W, float stride, int si, int a, int b, int bi, int nbase,
    float* __restrict__ det_out, float* __restrict__ keep_out)
{
    int h = s / W, w = s - h*W;
    float x  = (sigmoidf_(tx) + (float)w) * stride;
    float y  = (sigmoidf_(ty) + (float)h) * stride;
    float bw = expf(tw) * c_anch[si][a][0] * stride;
    float bh = expf(th) * c_anch[si][a][1] * stride;
    float conf = sigmoidf_(tc);

    float b0 = x - bw*0.5f, b1 = x + bw*0.5f;   // both from x (reference quirk)
    float b2 = y - bh*0.5f, b3 = y + bh*0.5f;   // both from y
    float area = fmaxf(b2-b0+1.0f, 0.0f) * fmaxf(b3-b1+1.0f, 0.0f);

    int n = nbase + (w*W + h)*3 + a;            // reference flatten order (W==H)
    long o = (long)b*NBOX + n;
    float* dp = det_out + o*6;
    dp[0]=b0; dp[1]=b1; dp[2]=b2; dp[3]=b3; dp[4]=conf; dp[5]=(float)bi;
    keep_out[o] = 0.0f;                          // NMS overwrites valid boxes

    if (conf > 0.5f){
        int bc = b*80 + bi;
        int pos = atomicAdd(&g_cnt[bc], 1);
        if (pos < CAP){
            float4* rec = (float4*)(g_bucket + ((long)bc*CAP + pos)*8);
            rec[0] = make_float4(b0, b1, b2, b3);
            rec[1] = make_float4(area, conf, (float)n, 0.0f);
        }
    }
}

// Hybrid decode: team of 4 lanes per spatial QUAD (scales 1,2; HW%4==0, aligned).
// Lane sub scans classes {sub, sub+4, ...} for all 4 cells at once (LDG.128),
// giving 100% sector efficiency AND 1268 warps of parallelism. Per-cell argmax
// merged across the 4 lanes (value, then smaller index -> exact first-occurrence).
// Lane sub then emits cell s4+sub. Scale 3 (HW=169, odd) uses a scalar tail.
__global__ void decode_kernel(const float* __restrict__ f1,
                              const float* __restrict__ f2,
                              const float* __restrict__ f3,
                              float* __restrict__ det_out,
                              float* __restrict__ keep_out){
    int T = blockIdx.x*blockDim.x + threadIdx.x;
    if (T < QEND){
        int team = T >> 2;
        int sub  = T & 3;
        bool valid = (team < NQT);
        if (team >= NQT) team = NQT - 1;         // clamp; keep full warps for shfl

        int a = team / (NBATCH*QTOT);
        int r = team - a*(NBATCH*QTOT);
        int b = r / QTOT;
        int q = r - b*QTOT;
        const float* feat; int W; float stride; int nbase; int HW; int si; int s4;
        if (q < 676){ feat=f1; W=52; stride=8.0f;  nbase=0;    HW=2704; si=0; s4=q*4; }
        else        { feat=f2; W=26; stride=16.0f; nbase=8112; HW=676;  si=1; s4=(q-676)*4; }

        const float* fc = feat + ((long)b*255 + a*85)*HW + s4;

        // Per-lane streaming argmax over 20 classes x 4 cells (float4 loads).
        const float* fcls = fc + 5L*HW;
        float4 best = *(const float4*)(fcls + (long)sub*HW);
        int bi0=sub, bi1=sub, bi2=sub, bi3=sub;
        #pragma unroll 5
        for (int i = 1; i < 20; i++){
            int e = sub + 4*i;
            float4 v = *(const float4*)(fcls + (long)e*HW);
            if (v.x > best.x){ best.x = v.x; bi0 = e; }
            if (v.y > best.y){ best.y = v.y; bi1 = e; }
            if (v.z > best.z){ best.z = v.z; bi2 = e; }
            if (v.w > best.w){ best.w = v.w; bi3 = e; }
        }
        // Merge per cell across the 4 lanes: larger value wins, tie -> smaller index.
        #pragma unroll
        for (int off = 1; off < 4; off <<= 1){
            float ox = __shfl_xor_sync(0xFFFFFFFFu, best.x, off);
            float oy = __shfl_xor_sync(0xFFFFFFFFu, best.y, off);
            float oz = __shfl_xor_sync(0xFFFFFFFFu, best.z, off);
            float ow = __shfl_xor_sync(0xFFFFFFFFu, best.w, off);
            int o0 = __shfl_xor_sync(0xFFFFFFFFu, bi0, off);
            int o1 = __shfl_xor_sync(0xFFFFFFFFu, bi1, off);
            int o2 = __shfl_xor_sync(0xFFFFFFFFu, bi2, off);
            int o3 = __shfl_xor_sync(0xFFFFFFFFu, bi3, off);
            if (ox > best.x || (ox == best.x && o0 < bi0)){ best.x = ox; bi0 = o0; }
            if (oy > best.y || (oy == best.y && o1 < bi1)){ best.y = oy; bi1 = o1; }
            if (oz > best.z || (oz == best.z && o2 < bi2)){ best.z = oz; bi2 = o2; }
            if (ow > best.w || (ow == best.w && o3 < bi3)){ best.w = ow; bi3 = o3; }
        }
        int bi = (sub==0)?bi0 : (sub==1)?bi1 : (sub==2)?bi2 : bi3;  // this lane's cell

        // Box params: lane sub loads channel sub (float4 over the 4 cells);
        // all lanes load channel 4 (same address per team -> warp-merged).
        float4 va  = *(const float4*)(fc + (long)sub*HW);
        float4 vc4 = *(const float4*)(fc + 4L*HW);
        int lbase = (threadIdx.x & 31) & ~3;
        float4 r0, r1, r2, r3;
        r0.x=__shfl_sync(0xFFFFFFFFu, va.x, lbase+0); r0.y=__shfl_sync(0xFFFFFFFFu, va.y, lbase+0);
        r0.z=__shfl_sync(0xFFFFFFFFu, va.z, lbase+0); r0.w=__shfl_sync(0xFFFFFFFFu, va.w, lbase+0);
        r1.x=__shfl_sync(0xFFFFFFFFu, va.x, lbase+1); r1.y=__shfl_sync(0xFFFFFFFFu, va.y, lbase+1);
        r1.z=__shfl_sync(0xFFFFFFFFu, va.z, lbase+1); r1.w=__shfl_sync(0xFFFFFFFFu, va.w, lbase+1);
        r2.x=__shfl_sync(0xFFFFFFFFu, va.x, lbase+2); r2.y=__shfl_sync(0xFFFFFFFFu, va.y, lbase+2);
        r2.z=__shfl_sync(0xFFFFFFFFu, va.z, lbase+2); r2.w=__shfl_sync(0xFFFFFFFFu, va.w, lbase+2);
        r3.x=__shfl_sync(0xFFFFFFFFu, va.x, lbase+3); r3.y=__shfl_sync(0xFFFFFFFFu, va.y, lbase+3);
        r3.z=__shfl_sync(0xFFFFFFFFu, va.z, lbase+3); r3.w=__shfl_sync(0xFFFFFFFFu, va.w, lbase+3);
        float tx = getc(r0, sub);   // channel 0, my cell
        float ty = getc(r1, sub);
        float tw = getc(r2, sub);
        float th = getc(r3, sub);
        float tc = getc(vc4, sub);

        if (valid)
            emit_box(tx,ty,tw,th,tc, s4+sub, W, stride, si, a, b, bi, nbase,
                     det_out, keep_out);
    }
    else if (T < DEC_TOTAL){
        // Scalar path (scale 3, HW=169: odd -> no aligned float4). One thread per box.
        int idx = T - QEND;
        int a = idx / (NBATCH*169);
        int r = idx - a*(NBATCH*169);
        int b = r / 169;
        int s = r - b*169;
        const float* fc = f3 + ((long)b*255 + a*85)*169 + s;
        float tx = fc[0], ty = fc[169], tw = fc[338], th = fc[507], tc = fc[676];
        const float* fcls = fc + 5*169;
        float best = fcls[0]; int bi = 0;
        #pragma unroll 8
        for (int e = 1; e < 80; e++){
            float v = fcls[e*169];
            if (v > best){ best = v; bi = e; }
        }
        emit_box(tx,ty,tw,th,tc, s, 13, 32.0f, 2, a, b, bi, 10140, det_out, keep_out);
    }
}

// R6 NMS (best measured): one block per bucket, vectorized smem + sentinel padding.
#define NMS_THREADS 512
__global__ void nms_kernel(float* __restrict__ keep_out){
    __shared__ float4 s_lo[CAP];     // b0,b1,b2,b3
    __shared__ float2 s_ac[CAP];     // area, conf
    __shared__ int    s_idx[CAP];

    int bc = blockIdx.x;                         // b*80 + c
    int b  = bc / 80;
    int t  = threadIdx.x;

    int cnt = g_cnt[bc]; if (cnt > CAP) cnt = CAP;
    int cntPad = (cnt + 31) & ~31;

    const float4* base = (const float4*)(g_bucket + (long)bc*CAP*8);
    for (int i = t; i < cntPad; i += NMS_THREADS){
        if (i < cnt){
            float4 lo = base[2*i], hi = base[2*i+1];
            s_lo[i] = lo;
            s_ac[i] = make_float2(hi.x, hi.y);
            s_idx[i] = (int)hi.z;
        } else {
            s_lo[i] = make_float4(0.f,0.f,0.f,0.f);
            s_ac[i] = make_float2(0.f, -CUDART_INF_F);   // sentinel: never a suppressor
        }
    }
    __syncthreads();
    if (t == 0) g_cnt[bc] = 0;                   // restore zero for next call

    int warp = t >> 5, lane = t & 31;
    for (int i = warp; i < cnt; i += (NMS_THREADS/32)){
        float4 il = s_lo[i];                     // warp-uniform broadcast
        float2 ia = s_ac[i];
        bool found = false;
        for (int j0 = 0; j0 < cntPad; j0 += 32){
            int j = j0 + lane;                   // always in-bounds (padded)
            float4 jl = s_lo[j];                 // one LDS.128
            float2 ja = s_ac[j];                 // one LDS.64
            bool p = (ia.y < ja.y);              // conf_i < conf_j (false on pads & j==i)
            if (p){
                float wI = fminf(il.z, jl.z) - fmaxf(il.x, jl.x) + 1.0f;
                float hI = fminf(il.w, jl.w) - fmaxf(il.y, jl.y) + 1.0f;
                wI = fmaxf(wI, 0.0f); hI = fmaxf(hI, 0.0f);
                float inter = wI * hI;
                p = (inter > 0.0f) &&            // inter==0 -> ref iou 0 or NaN -> false
                    (inter / (ia.x + ja.x - inter) > 0.4f);  // same op order, IEEE div
            }
            if (__any_sync(0xFFFFFFFFu, p)){ found = true; break; }
        }
        if (lane == 0)
            keep_out[(long)b*NBOX + s_idx[i]] = found ? 1.0f : 0.0f;
    }
}

extern "C" void kernel_launch(void* const* d_in, const int* in_sizes, int n_in,
                              void* d_out, int out_size){
    const float* f1 = (const float*)d_in[0];   // (4,255,52,52)
    const float* f2 = (const float*)d_in[1];   // (4,255,26,26)
    const float* f3 = (const float*)d_in[2];   // (4,255,13,13)
    float* det  = (float*)d_out;               // (4,10647,6) then keep (4,10647)
    float* keep = det + DET_ELEMS;

    decode_kernel<<<(DEC_TOTAL + 127)/128, 128>>>(f1, f2, f3, det, keep);
    nms_kernel   <<<NBATCH*80, NMS_THREADS>>>(keep);
}

// round 12
// speedup vs baseline: 1.3283x; 1.0589x over previous
#include <cuda_runtime.h>
#include <math_constants.h>

#define NBOX   10647          // 52*52*3 + 26*26*3 + 13*13*3
#define NBATCH 4
#define DET_ELEMS (NBATCH*NBOX*6)
#define CAP    256            // per-(batch,class) bucket capacity (mean ~66, >20 sigma safe)

#define QTOT    845           // float4-quads over scale1+scale2 spatial (676 + 169)
#define NQT     (3*NBATCH*QTOT)              // 10140 quad-teams
#define QTHREADS (NQT*4)                     // 40560 quad lanes
#define QEND    (((QTHREADS)+31) & ~31)      // 40576: pad to warp boundary
#define S3THREADS (3*NBATCH*169)             // 2028 scalar threads (scale 3)
#define DEC_TOTAL (QEND + S3THREADS)         // 42604

// Scratch (__device__ globals — zero-initialized at load; nms re-zeroes g_cnt after use)
__device__ int   g_cnt[NBATCH*80];
__device__ float g_bucket[NBATCH*80*CAP*8];  // b0,b1,b2,b3 | area,conf,idx,pad

__constant__ float c_anch[3][3][2] = {
  {{10.f,13.f},{16.f,30.f},{33.f,23.f}},
  {{30.f,61.f},{62.f,45.f},{59.f,119.f}},
  {{116.f,90.f},{156.f,198.f},{373.f,326.f}}
};

__device__ __forceinline__ float sigmoidf_(float x){ return 1.0f/(1.0f + expf(-x)); }
__device__ __forceinline__ float getc(float4 v, int k){
    return (k==0)?v.x : (k==1)?v.y : (k==2)?v.z : v.w;
}

// Full per-box epilogue: reference math (same op order), det/keep stores, bucket append.
__device__ __forceinline__ void emit_box(
    float tx, float ty, float tw, float th, float tc,
    int s, int W, float stride, int si, int a, int b, int bi, int nbase,
    float* __restrict__ det_out, float* __restrict__ keep_out)
{
    int h = s / W, w = s - h*W;
    float x  = (sigmoidf_(tx) + (float)w) * stride;
    float y  = (sigmoidf_(ty) + (float)h) * stride;
    float bw = expf(tw) * c_anch[si][a][0] * stride;
    float bh = expf(th) * c_anch[si][a][1] * stride;
    float conf = sigmoidf_(tc);

    float b0 = x - bw*0.5f, b1 = x + bw*0.5f;   // both from x (reference quirk)
    float b2 = y - bh*0.5f, b3 = y + bh*0.5f;   // both from y
    float area = fmaxf(b2-b0+1.0f, 0.0f) * fmaxf(b3-b1+1.0f, 0.0f);

    int n = nbase + (w*W + h)*3 + a;            // reference flatten order (W==H)
    long o = (long)b*NBOX + n;
    float* dp = det_out + o*6;
    dp[0]=b0; dp[1]=b1; dp[2]=b2; dp[3]=b3; dp[4]=conf; dp[5]=(float)bi;
    keep_out[o] = 0.0f;                          // NMS overwrites valid boxes

    if (conf > 0.5f){
        int bc = b*80 + bi;
        int pos = atomicAdd(&g_cnt[bc], 1);
        if (pos < CAP){
            float4* rec = (float4*)(g_bucket + ((long)bc*CAP + pos)*8);
            rec[0] = make_float4(b0, b1, b2, b3);
            rec[1] = make_float4(area, conf, (float)n, 0.0f);
        }
    }
}

// Hybrid decode (R11, validated): team of 4 lanes per spatial quad; float4 loads,
// exact first-occurrence argmax via (value, smaller-index) merge.
__global__ void decode_kernel(const float* __restrict__ f1,
                              const float* __restrict__ f2,
                              const float* __restrict__ f3,
                              float* __restrict__ det_out,
                              float* __restrict__ keep_out){
    int T = blockIdx.x*blockDim.x + threadIdx.x;
    if (T < QEND){
        int team = T >> 2;
        int sub  = T & 3;
        bool valid = (team < NQT);
        if (team >= NQT) team = NQT - 1;         // clamp; keep full warps for shfl

        int a = team / (NBATCH*QTOT);
        int r = team - a*(NBATCH*QTOT);
        int b = r / QTOT;
        int q = r - b*QTOT;
        const float* feat; int W; float stride; int nbase; int HW; int si; int s4;
        if (q < 676){ feat=f1; W=52; stride=8.0f;  nbase=0;    HW=2704; si=0; s4=q*4; }
        else        { feat=f2; W=26; stride=16.0f; nbase=8112; HW=676;  si=1; s4=(q-676)*4; }

        const float* fc = feat + ((long)b*255 + a*85)*HW + s4;

        const float* fcls = fc + 5L*HW;
        float4 best = *(const float4*)(fcls + (long)sub*HW);
        int bi0=sub, bi1=sub, bi2=sub, bi3=sub;
        #pragma unroll 5
        for (int i = 1; i < 20; i++){
            int e = sub + 4*i;
            float4 v = *(const float4*)(fcls + (long)e*HW);
            if (v.x > best.x){ best.x = v.x; bi0 = e; }
            if (v.y > best.y){ best.y = v.y; bi1 = e; }
            if (v.z > best.z){ best.z = v.z; bi2 = e; }
            if (v.w > best.w){ best.w = v.w; bi3 = e; }
        }
        #pragma unroll
        for (int off = 1; off < 4; off <<= 1){
            float ox = __shfl_xor_sync(0xFFFFFFFFu, best.x, off);
            float oy = __shfl_xor_sync(0xFFFFFFFFu, best.y, off);
            float oz = __shfl_xor_sync(0xFFFFFFFFu, best.z, off);
            float ow = __shfl_xor_sync(0xFFFFFFFFu, best.w, off);
            int o0 = __shfl_xor_sync(0xFFFFFFFFu, bi0, off);
            int o1 = __shfl_xor_sync(0xFFFFFFFFu, bi1, off);
            int o2 = __shfl_xor_sync(0xFFFFFFFFu, bi2, off);
            int o3 = __shfl_xor_sync(0xFFFFFFFFu, bi3, off);
            if (ox > best.x || (ox == best.x && o0 < bi0)){ best.x = ox; bi0 = o0; }
            if (oy > best.y || (oy == best.y && o1 < bi1)){ best.y = oy; bi1 = o1; }
            if (oz > best.z || (oz == best.z && o2 < bi2)){ best.z = oz; bi2 = o2; }
            if (ow > best.w || (ow == best.w && o3 < bi3)){ best.w = ow; bi3 = o3; }
        }
        int bi = (sub==0)?bi0 : (sub==1)?bi1 : (sub==2)?bi2 : bi3;  // this lane's cell

        float4 va  = *(const float4*)(fc + (long)sub*HW);
        float4 vc4 = *(const float4*)(fc + 4L*HW);
        int lbase = (threadIdx.x & 31) & ~3;
        float4 r0, r1, r2, r3;
        r0.x=__shfl_sync(0xFFFFFFFFu, va.x, lbase+0); r0.y=__shfl_sync(0xFFFFFFFFu, va.y, lbase+0);
        r0.z=__shfl_sync(0xFFFFFFFFu, va.z, lbase+0); r0.w=__shfl_sync(0xFFFFFFFFu, va.w, lbase+0);
        r1.x=__shfl_sync(0xFFFFFFFFu, va.x, lbase+1); r1.y=__shfl_sync(0xFFFFFFFFu, va.y, lbase+1);
        r1.z=__shfl_sync(0xFFFFFFFFu, va.z, lbase+1); r1.w=__shfl_sync(0xFFFFFFFFu, va.w, lbase+1);
        r2.x=__shfl_sync(0xFFFFFFFFu, va.x, lbase+2); r2.y=__shfl_sync(0xFFFFFFFFu, va.y, lbase+2);
        r2.z=__shfl_sync(0xFFFFFFFFu, va.z, lbase+2); r2.w=__shfl_sync(0xFFFFFFFFu, va.w, lbase+2);
        r3.x=__shfl_sync(0xFFFFFFFFu, va.x, lbase+3); r3.y=__shfl_sync(0xFFFFFFFFu, va.y, lbase+3);
        r3.z=__shfl_sync(0xFFFFFFFFu, va.z, lbase+3); r3.w=__shfl_sync(0xFFFFFFFFu, va.w, lbase+3);
        float tx = getc(r0, sub);
        float ty = getc(r1, sub);
        float tw = getc(r2, sub);
        float th = getc(r3, sub);
        float tc = getc(vc4, sub);

        if (valid)
            emit_box(tx,ty,tw,th,tc, s4+sub, W, stride, si, a, b, bi, nbase,
                     det_out, keep_out);
    }
    else if (T < DEC_TOTAL){
        int idx = T - QEND;
        int a = idx / (NBATCH*169);
        int r = idx - a*(NBATCH*169);
        int b = r / 169;
        int s = r - b*169;
        const float* fc = f3 + ((long)b*255 + a*85)*169 + s;
        float tx = fc[0], ty = fc[169], tw = fc[338], th = fc[507], tc = fc[676];
        const float* fcls = fc + 5*169;
        float best = fcls[0]; int bi = 0;
        #pragma unroll 8
        for (int e = 1; e < 80; e++){
            float v = fcls[e*169];
            if (v > best){ best = v; bi = e; }
        }
        emit_box(tx,ty,tw,th,tc, s, 13, 32.0f, 2, a, b, bi, 10140, det_out, keep_out);
    }
}

// R6/R11 NMS body, launched with PDL: blocks start during decode, pre-fill smem
// sentinels, then cudaGridDependencySynchronize() waits for decode completion.
#define NMS_THREADS 512
__global__ void nms_kernel(float* __restrict__ keep_out){
    __shared__ float4 s_lo[CAP];     // b0,b1,b2,b3
    __shared__ float2 s_ac[CAP];     // area, conf
    __shared__ int    s_idx[CAP];

    int bc = blockIdx.x;                         // b*80 + c
    int b  = bc / 80;
    int t  = threadIdx.x;

    // ---- prelude: overlaps with decode under PDL ----
    for (int i = t; i < CAP; i += NMS_THREADS){
        s_lo[i] = make_float4(0.f,0.f,0.f,0.f);
        s_ac[i] = make_float2(0.f, -CUDART_INF_F);       // sentinel everywhere
    }
    __syncthreads();

    cudaGridDependencySynchronize();             // wait for decode grid to complete

    int cnt = g_cnt[bc]; if (cnt > CAP) cnt = CAP;
    int cntPad = (cnt + 31) & ~31;

    const float4* base = (const float4*)(g_bucket + (long)bc*CAP*8);
    for (int i = t; i < cnt; i += NMS_THREADS){  // overwrite [0,cnt); pads stay sentinel
        float4 lo = base[2*i], hi = base[2*i+1];
        s_lo[i] = lo;
        s_ac[i] = make_float2(hi.x, hi.y);
        s_idx[i] = (int)hi.z;
    }
    __syncthreads();
    if (t == 0) g_cnt[bc] = 0;                   // restore zero for next call

    int warp = t >> 5, lane = t & 31;
    for (int i = warp; i < cnt; i += (NMS_THREADS/32)){
        float4 il = s_lo[i];                     // warp-uniform broadcast
        float2 ia = s_ac[i];
        bool found = false;
        for (int j0 = 0; j0 < cntPad; j0 += 32){
            int j = j0 + lane;                   // always in-bounds (padded)
            float4 jl = s_lo[j];                 // one LDS.128
            float2 ja = s_ac[j];                 // one LDS.64
            bool p = (ia.y < ja.y);              // conf_i < conf_j (false on pads & j==i)
            if (p){
                float wI = fminf(il.z, jl.z) - fmaxf(il.x, jl.x) + 1.0f;
                float hI = fminf(il.w, jl.w) - fmaxf(il.y, jl.y) + 1.0f;
                wI = fmaxf(wI, 0.0f); hI = fmaxf(hI, 0.0f);
                float inter = wI * hI;
                p = (inter > 0.0f) &&            // inter==0 -> ref iou 0 or NaN -> false
                    (inter / (ia.x + ja.x - inter) > 0.4f);  // same op order, IEEE div
            }
            if (__any_sync(0xFFFFFFFFu, p)){ found = true; break; }
        }
        if (lane == 0)
            keep_out[(long)b*NBOX + s_idx[i]] = found ? 1.0f : 0.0f;
    }
}

extern "C" void kernel_launch(void* const* d_in, const int* in_sizes, int n_in,
                              void* d_out, int out_size){
    const float* f1 = (const float*)d_in[0];   // (4,255,52,52)
    const float* f2 = (const float*)d_in[1];   // (4,255,26,26)
    const float* f3 = (const float*)d_in[2];   // (4,255,13,13)
    float* det  = (float*)d_out;               // (4,10647,6) then keep (4,10647)
    float* keep = det + DET_ELEMS;

    decode_kernel<<<(DEC_TOTAL + 127)/128, 128>>>(f1, f2, f3, det, keep);

    // NMS with programmatic dependent launch: overlap launch+prelude with decode.
    cudaLaunchConfig_t cfg = {};
    cfg.gridDim  = dim3(NBATCH*80, 1, 1);
    cfg.blockDim = dim3(NMS_THREADS, 1, 1);
    cfg.dynamicSmemBytes = 0;
    cfg.stream = 0;                              // same (legacy default) stream
    cudaLaunchAttribute attr[1];
    attr[0].id = cudaLaunchAttributeProgrammaticStreamSerialization;
    attr[0].val.programmaticStreamSerializationAllowed = 1;
    cfg.attrs = attr;
    cfg.numAttrs = 1;
    cudaLaunchKernelEx(&cfg, nms_kernel, keep);
}